// round 7
// baseline (speedup 1.0000x reference)
#include <cuda_runtime.h>
#include <math.h>

#define B_    4
#define NPTS  8192
#define KNN   9
#define TPB   256
#define QPB   256                  // queries per scan block
#define KTPB  512                  // 256 queries x 2 sides
#define CAP   128                  // record capacity per (query,side)
#define NPOINTS (B_*NPTS)          // 32768
#define NROWS   (NPOINTS*KNN)      // 294912
#define NB1     (NPOINTS/TPB)      // 128
#define NB3     (NROWS/TPB)        // 1152
#define EPS_BN  1e-5f

// ---- scratch (static device memory; no allocations) ----
__device__ float4   g_sp[NPOINTS];            // sorted points (x,y,z,|p|^2)
__device__ int      g_sid[NPOINTS];           // sorted pos -> original id
__device__ unsigned g_rec[(size_t)NPOINTS*2*CAP];  // insert-event records
__device__ int      g_nbr[(size_t)NPOINTS*KNN];
__device__ __align__(16) float g_h1[(size_t)NROWS*10];
__device__ __align__(16) float g_h2[(size_t)NROWS*10];
__device__ float g_part1[NB1*20];
__device__ float g_part2[NB3*20];
__device__ float g_coef1[20];
__device__ float g_coef2[20];

// branchless insert of one value into sorted-ascending s[0..9] (values only)
#define CHAIN_INSERT(sarr, val) do {                 \
    float _c = (val);                                \
    _Pragma("unroll")                                \
    for (int _j = 0; _j < 10; _j++) {                \
        float _lo = fminf(sarr[_j], _c);             \
        _c = fmaxf(sarr[_j], _c);                    \
        sarr[_j] = _lo;                              \
    }                                                \
} while (0)

// =====================================================================
// Kernel 0: per-batch bitonic sort by x-coordinate
// =====================================================================
__global__ void __launch_bounds__(1024) k_sort(const float* __restrict__ x)
{
    extern __shared__ unsigned char smem_raw[];
    float* sk = (float*)smem_raw;                // [NPTS]
    int*   si = (int*)(sk + NPTS);               // [NPTS]

    const int b = blockIdx.x;
    const int t = threadIdx.x;
    const float* xb = x + (size_t)b*NPTS*3;

    for (int i = t; i < NPTS; i += 1024) { sk[i] = xb[3*i]; si[i] = i; }

    for (int k = 2; k <= NPTS; k <<= 1) {
        for (int j = k >> 1; j > 0; j >>= 1) {
            __syncthreads();
            for (int i = t; i < NPTS; i += 1024) {
                int ixj = i ^ j;
                if (ixj > i) {
                    bool up = ((i & k) == 0);
                    float a = sk[i], c = sk[ixj];
                    bool sw = up ? (a > c) : (a < c);
                    if (sw) {
                        sk[i] = c; sk[ixj] = a;
                        int tmp = si[i]; si[i] = si[ixj]; si[ixj] = tmp;
                    }
                }
            }
        }
    }
    __syncthreads();

    for (int i = t; i < NPTS; i += 1024) {
        int id = si[i];
        float px = xb[3*id+0], py = xb[3*id+1], pz = xb[3*id+2];
        g_sp[(size_t)b*NPTS + i] = make_float4(px, py, pz, px*px + py*py + pz*pz);
        g_sid[(size_t)b*NPTS + i] = id;
    }
}

// =====================================================================
// Kernel A: kNN via sorted-axis outward scan with exact termination.
//           2 threads per query (right side / left side).
// =====================================================================
__global__ void __launch_bounds__(KTPB, 1) k_knn()
{
    extern __shared__ unsigned char smem_raw[];
    float4*         sp   = (float4*)smem_raw;                       // [NPTS]
    unsigned short* ssid = (unsigned short*)(smem_raw + NPTS*sizeof(float4)); // [NPTS]

    const int t    = threadIdx.x;
    const int b    = blockIdx.x >> 5;
    const int posbase = (blockIdx.x & 31) * QPB;
    const int qsl  = t >> 1;                 // query slot 0..255
    const int side = t & 1;                  // 0 = right (incl self), 1 = left
    const int pos  = posbase + qsl;          // sorted position of the query

    for (int i = t; i < NPTS; i += KTPB) {
        sp[i]   = g_sp[(size_t)b*NPTS + i];
        ssid[i] = (unsigned short)g_sid[(size_t)b*NPTS + i];
    }
    __syncthreads();

    const float4 q = sp[pos];
    const float qq  = q.w;
    const float nqx = -2.f*q.x, nqy = -2.f*q.y, nqz = -2.f*q.z;

    float s[10];
    #pragma unroll
    for (int j = 0; j < 10; j++) s[j] = 3.4e38f;
    float bnd = 3.4e38f;    // (s[9]+qq)*1.01+1e-6 once top-10 is full

    unsigned* rec = g_rec + (size_t)(blockIdx.x*KTPB + t)*CAP;
    int cnt = 0;

    const int start = side ? pos-1 : pos;
    const int step  = side ? -1 : 1;

    #pragma unroll 1
    for (int i = start; (unsigned)i < NPTS; i += step) {
        float4 p = sp[i];
        float dx = p.x - q.x;
        if (dx*dx > bnd) break;               // sorted x => valid for all further i
        float sv = fmaf(p.x, nqx, p.w);
        sv = fmaf(p.y, nqy, sv);
        sv = fmaf(p.z, nqz, sv);
        if (sv <= s[9]) {                     // record running-top-10 membership (incl. ties)
            if (cnt < CAP) rec[cnt] = (unsigned)i;
            cnt++;
            if (sv < s[9]) {
                CHAIN_INSERT(s, sv);
                bnd = (s[9] + qq)*1.01f + 1e-6f;
            }
        }
    }

    __syncthreads();                          // make partner's records visible

    const int cntP = __shfl_xor_sync(0xffffffffu, cnt, 1);

    if (side == 0) {
        // exact top-10 by (s, original id) over recorded superset
        float v[10]; int vid[10];
        #pragma unroll
        for (int j = 0; j < 10; j++) { v[j] = 3.4e38f; vid[j] = 0x7fffffff; }

        const unsigned* recP = g_rec + (size_t)(blockIdx.x*KTPB + (t|1))*CAP;
        const int m0 = cnt  < CAP ? cnt  : CAP;
        const int m1 = cntP < CAP ? cntP : CAP;

        for (int h = 0; h < 2; h++) {
            const unsigned* L = h ? recP : rec;
            const int       M = h ? m1   : m0;
            #pragma unroll 1
            for (int r = 0; r < M; r++) {
                unsigned spos = L[r];
                float4 p = sp[spos];
                float sv = fmaf(p.x, nqx, p.w);
                sv = fmaf(p.y, nqy, sv);
                sv = fmaf(p.z, nqz, sv);
                int oid = (int)ssid[spos];
                if (sv < v[9] || (sv == v[9] && oid < vid[9])) {
                    float cs = sv; int ci = oid;
                    #pragma unroll
                    for (int j = 0; j < 10; j++) {
                        bool take = (cs < v[j]) || (cs == v[j] && ci < vid[j]);
                        float tv = take ? cs : v[j];
                        float uv = take ? v[j] : cs;
                        int   ti = take ? ci : vid[j];
                        int   ui = take ? vid[j] : ci;
                        v[j] = tv; vid[j] = ti; cs = uv; ci = ui;
                    }
                }
            }
        }

        // v[0] is self (distance 0, strict minimum); keep 1..9 in (d,idx) order
        const int qoid = (int)ssid[pos];
        int* dst = g_nbr + (size_t)(b*NPTS + qoid)*KNN;
        #pragma unroll
        for (int j = 1; j < 10; j++) dst[j-1] = vid[j];
    }
}

// =====================================================================
// Kernel B: angular features + GEMM1 + stats1
// =====================================================================
__global__ void __launch_bounds__(TPB) k_feat(const float* __restrict__ x,
                                              const float* __restrict__ W1,
                                              const float* __restrict__ b1)
{
    __shared__ float sW1[70], sB1[10], sRed[(TPB/32)*20];
    const int t = threadIdx.x;
    if (t < 70) sW1[t] = W1[t];
    if (t < 10) sB1[t] = b1[t];
    __syncthreads();

    const int p = blockIdx.x*TPB + t;
    const int b = p / NPTS;
    const int n = p % NPTS;
    const float* xb = x + (size_t)b*NPTS*3;
    const float qx = xb[3*n+0], qy = xb[3*n+1], qz = xb[3*n+2];

    const int* ids = g_nbr + (size_t)p*KNN;
    float rx[KNN], ry[KNN], rz[KNN], ph[KNN];
    #pragma unroll
    for (int j = 0; j < KNN; j++) {
        int id = ids[j];
        rx[j] = xb[3*id+0] - qx;
        ry[j] = xb[3*id+1] - qy;
        rz[j] = xb[3*id+2] - qz;
        ph[j] = atan2f(ry[j], rx[j]);
    }

    #pragma unroll
    for (int pass = 0; pass < KNN-1; pass++) {
        #pragma unroll
        for (int j = 0; j < KNN-1; j++) {
            if (j < KNN-1-pass) {
                if (ph[j+1] < ph[j]) {
                    float tt;
                    tt = ph[j]; ph[j] = ph[j+1]; ph[j+1] = tt;
                    tt = rx[j]; rx[j] = rx[j+1]; rx[j+1] = tt;
                    tt = ry[j]; ry[j] = ry[j+1]; ry[j+1] = tt;
                    tt = rz[j]; rz[j] = rz[j+1]; rz[j+1] = tt;
                }
            }
        }
    }

    float sum[10], sq[10];
    #pragma unroll
    for (int c = 0; c < 10; c++) { sum[c] = 0.f; sq[c] = 0.f; }

    float sgn = 1.f;
    const size_t rowbase = (size_t)p * KNN * 10;
    #pragma unroll
    for (int i = 0; i < KNN; i++) {
        const int i2 = (i+1) % KNN;
        float v1x = rx[i],  v1y = ry[i],  v1z = rz[i];
        float v2x = rx[i2], v2y = ry[i2], v2z = rz[i2];
        float cx = 0.5f*(v1x+v2x), cy = 0.5f*(v1y+v2y), cz = 0.5f*(v1z+v2z);
        float nx = v1y*v2z - v1z*v2y;
        float ny = v1z*v2x - v1x*v2z;
        float nz = v1x*v2y - v1y*v2x;
        float nrm = sqrtf(nx*nx + ny*ny + nz*nz);
        float inv = 1.f/(nrm + 1e-6f);
        nx *= inv; ny *= inv; nz *= inv;
        if (i == 0) sgn = (nx > 0.f) ? 1.f : -1.f;
        nx *= sgn; ny *= sgn; nz *= sgn;
        float pos7 = (nx*cx + ny*cy + nz*cz) * 0.57735026918962576f;

        float f[7] = {cx, cy, cz, nx, ny, nz, pos7};
        #pragma unroll
        for (int c = 0; c < 10; c++) {
            float h = sB1[c];
            #pragma unroll
            for (int ff = 0; ff < 7; ff++) h = fmaf(f[ff], sW1[ff*10 + c], h);
            g_h1[rowbase + i*10 + c] = h;
            sum[c] += h;
            sq[c]  = fmaf(h, h, sq[c]);
        }
    }

    #pragma unroll
    for (int c = 0; c < 10; c++) {
        #pragma unroll
        for (int o = 16; o > 0; o >>= 1) {
            sum[c] += __shfl_down_sync(0xffffffffu, sum[c], o);
            sq[c]  += __shfl_down_sync(0xffffffffu, sq[c],  o);
        }
    }
    const int warp = t >> 5, lane = t & 31;
    if (lane == 0) {
        #pragma unroll
        for (int c = 0; c < 10; c++) {
            sRed[warp*20 + c]      = sum[c];
            sRed[warp*20 + 10 + c] = sq[c];
        }
    }
    __syncthreads();
    if (t < 20) {
        float acc = 0.f;
        #pragma unroll
        for (int w = 0; w < TPB/32; w++) acc += sRed[w*20 + t];
        g_part1[blockIdx.x*20 + t] = acc;
    }
}

// =====================================================================
// Parallel BN-stats finalize
// =====================================================================
__device__ __forceinline__ void fin_body(const float* __restrict__ part, int nblk,
                                         const float* __restrict__ g,
                                         const float* __restrict__ be,
                                         float* __restrict__ coef)
{
    __shared__ float red[32*20];
    __shared__ float tot[20];
    const int t = threadIdx.x;
    const int c = t % 20, sub = t / 20;
    float acc = 0.f;
    for (int k = sub; k < nblk; k += 32) acc += part[k*20 + c];
    red[sub*20 + c] = acc;
    __syncthreads();
    if (t < 20) {
        float s = 0.f;
        #pragma unroll
        for (int w = 0; w < 32; w++) s += red[w*20 + t];
        tot[t] = s;
    }
    __syncthreads();
    if (t < 10) {
        float mu  = tot[t] / (float)NROWS;
        float var = tot[10 + t] / (float)NROWS - mu*mu;
        float a   = g[t] * rsqrtf(var + EPS_BN);
        coef[t]      = a;
        coef[10 + t] = be[t] - mu*a;
    }
}

__global__ void k_fin1(const float* __restrict__ g1, const float* __restrict__ be1)
{ fin_body(g_part1, NB1, g1, be1, g_coef1); }

__global__ void k_fin2(const float* __restrict__ g2, const float* __restrict__ be2)
{ fin_body(g_part2, NB3, g2, be2, g_coef2); }

// =====================================================================
// Kernel 3: BN1 + relu + GEMM2 + stats2  (float2 I/O)
// =====================================================================
__global__ void __launch_bounds__(TPB) k_mlp2(const float* __restrict__ W2,
                                              const float* __restrict__ b2)
{
    __shared__ float sW2[100], sB2[10], sA[10], sC[10], sRed[(TPB/32)*20];
    const int t = threadIdx.x;
    if (t < 100) sW2[t] = W2[t];
    if (t < 10) { sB2[t] = b2[t]; sA[t] = g_coef1[t]; sC[t] = g_coef1[10+t]; }
    __syncthreads();

    const size_t row = (size_t)blockIdx.x*TPB + t;
    const float2* src2 = (const float2*)(g_h1 + row*10);

    float h[10];
    #pragma unroll
    for (int c = 0; c < 5; c++) {
        float2 v = src2[c];
        h[2*c+0] = fmaxf(fmaf(v.x, sA[2*c+0], sC[2*c+0]), 0.f);
        h[2*c+1] = fmaxf(fmaf(v.y, sA[2*c+1], sC[2*c+1]), 0.f);
    }

    float sum[10], sq[10];
    float2* dst2 = (float2*)(g_h2 + row*10);
    #pragma unroll
    for (int c2 = 0; c2 < 10; c2++) {
        float z = sB2[c2];
        #pragma unroll
        for (int c = 0; c < 10; c++) z = fmaf(h[c], sW2[c*10 + c2], z);
        sum[c2] = z;
        sq[c2]  = z*z;
    }
    #pragma unroll
    for (int c = 0; c < 5; c++) dst2[c] = make_float2(sum[2*c], sum[2*c+1]);

    #pragma unroll
    for (int c = 0; c < 10; c++) {
        #pragma unroll
        for (int o = 16; o > 0; o >>= 1) {
            sum[c] += __shfl_down_sync(0xffffffffu, sum[c], o);
            sq[c]  += __shfl_down_sync(0xffffffffu, sq[c],  o);
        }
    }
    const int warp = t >> 5, lane = t & 31;
    if (lane == 0) {
        #pragma unroll
        for (int c = 0; c < 10; c++) {
            sRed[warp*20 + c]      = sum[c];
            sRed[warp*20 + 10 + c] = sq[c];
        }
    }
    __syncthreads();
    if (t < 20) {
        float acc = 0.f;
        #pragma unroll
        for (int w = 0; w < TPB/32; w++) acc += sRed[w*20 + t];
        g_part2[blockIdx.x*20 + t] = acc;
    }
}

// =====================================================================
// Kernel 5: BN2 + relu + max over k  (float2 I/O)
// =====================================================================
__global__ void __launch_bounds__(TPB) k_out(float* __restrict__ out)
{
    __shared__ float sA[10], sC[10];
    if (threadIdx.x < 10) { sA[threadIdx.x] = g_coef2[threadIdx.x]; sC[threadIdx.x] = g_coef2[10+threadIdx.x]; }
    __syncthreads();

    const size_t p = (size_t)blockIdx.x*TPB + threadIdx.x;
    const float2* src2 = (const float2*)(g_h2 + p*KNN*10);

    float mx[10];
    #pragma unroll
    for (int c = 0; c < 10; c++) mx[c] = 0.f;

    #pragma unroll
    for (int i = 0; i < KNN; i++) {
        #pragma unroll
        for (int c = 0; c < 5; c++) {
            float2 v = src2[i*5 + c];
            mx[2*c+0] = fmaxf(mx[2*c+0], fmaxf(fmaf(v.x, sA[2*c+0], sC[2*c+0]), 0.f));
            mx[2*c+1] = fmaxf(mx[2*c+1], fmaxf(fmaf(v.y, sA[2*c+1], sC[2*c+1]), 0.f));
        }
    }
    float2* o2 = (float2*)(out + p*10);
    #pragma unroll
    for (int c = 0; c < 5; c++) o2[c] = make_float2(mx[2*c], mx[2*c+1]);
}

// =====================================================================
extern "C" void kernel_launch(void* const* d_in, const int* in_sizes, int n_in,
                              void* d_out, int out_size)
{
    const float* x   = (const float*)d_in[0];
    const float* W1  = (const float*)d_in[1];
    const float* b1  = (const float*)d_in[2];
    const float* g1  = (const float*)d_in[3];
    const float* be1 = (const float*)d_in[4];
    const float* W2  = (const float*)d_in[5];
    const float* b2  = (const float*)d_in[6];
    const float* g2  = (const float*)d_in[7];
    const float* be2 = (const float*)d_in[8];
    float* out = (float*)d_out;

    const size_t smemSort = (size_t)NPTS*(sizeof(float)+sizeof(int));       // 64KB
    const size_t smemKnn  = (size_t)NPTS*sizeof(float4)
                          + (size_t)NPTS*sizeof(unsigned short);            // 144KB
    cudaFuncSetAttribute(k_sort, cudaFuncAttributeMaxDynamicSharedMemorySize, (int)smemSort);
    cudaFuncSetAttribute(k_knn,  cudaFuncAttributeMaxDynamicSharedMemorySize, (int)smemKnn);

    k_sort<<<B_, 1024, smemSort>>>(x);
    k_knn<<<NPOINTS/QPB, KTPB, smemKnn>>>();
    k_feat<<<NB1, TPB>>>(x, W1, b1);
    k_fin1<<<1, 640>>>(g1, be1);
    k_mlp2<<<NB3, TPB>>>(W2, b2);
    k_fin2<<<1, 640>>>(g2, be2);
    k_out<<<NPOINTS/TPB, TPB>>>(out);
}

// round 10
// speedup vs baseline: 1.5496x; 1.5496x over previous
#include <cuda_runtime.h>
#include <math.h>

#define B_    4
#define NPTS  8192
#define KNN   9
#define TPB   256
#define SCANT 256                  // scan threads/block = queries/block
#define PAD   8
#define CAP   192                  // record capacity per query
#define BNDMAX 1e37f               // finite bound cap (sentinel dx^2 = inf always exceeds)
#define NPOINTS (B_*NPTS)          // 32768
#define NROWS   (NPOINTS*KNN)      // 294912
#define NB1     (NPOINTS/TPB)      // 128
#define NB3     (NROWS/TPB)        // 1152
#define EPS_BN  1e-5f

// ---- scratch (static device memory; no allocations) ----
__device__ float4   g_sp[NPOINTS];                 // sorted points (x,y,z,|p|^2)
__device__ int      g_sid[NPOINTS];                // sorted pos -> original id
__device__ unsigned g_rec[(size_t)NPOINTS*CAP];    // insert-event records
__device__ int      g_nbr[(size_t)NPOINTS*KNN];
__device__ __align__(16) float g_h1[(size_t)NROWS*10];
__device__ __align__(16) float g_h2[(size_t)NROWS*10];
__device__ float g_part1[NB1*20];
__device__ float g_part2[NB3*20];
__device__ float g_coef1[20];
__device__ float g_coef2[20];

// branchless insert of one value into sorted-ascending s[0..9] (values only)
#define CHAIN_INSERT(sarr, val) do {                 \
    float _c = (val);                                \
    _Pragma("unroll")                                \
    for (int _j = 0; _j < 10; _j++) {                \
        float _lo = fminf(sarr[_j], _c);             \
        _c = fmaxf(sarr[_j], _c);                    \
        sarr[_j] = _lo;                              \
    }                                                \
} while (0)

// exact lexicographic (value, id) insert into ascending (v, vid)[0..9]
__device__ __forceinline__ void lex_insert(float* v, int* vid, float sv, int oid) {
    if (sv < v[9] || (sv == v[9] && oid < vid[9])) {
        float cs = sv; int ci = oid;
        #pragma unroll
        for (int j = 0; j < 10; j++) {
            bool take = (cs < v[j]) || (cs == v[j] && ci < vid[j]);
            float tv = take ? cs : v[j];
            float uv = take ? v[j] : cs;
            int   ti = take ? ci : vid[j];
            int   ui = take ? vid[j] : ci;
            v[j] = tv; vid[j] = ti; cs = uv; ci = ui;
        }
    }
}

// =====================================================================
// Kernel 0: per-batch bitonic sort by x-coordinate
// =====================================================================
__global__ void __launch_bounds__(1024) k_sort(const float* __restrict__ x)
{
    extern __shared__ unsigned char smem_raw[];
    float* sk = (float*)smem_raw;                // [NPTS]
    int*   si = (int*)(sk + NPTS);               // [NPTS]

    const int b = blockIdx.x;
    const int t = threadIdx.x;
    const float* xb = x + (size_t)b*NPTS*3;

    for (int i = t; i < NPTS; i += 1024) { sk[i] = xb[3*i]; si[i] = i; }

    for (int k = 2; k <= NPTS; k <<= 1) {
        for (int j = k >> 1; j > 0; j >>= 1) {
            __syncthreads();
            for (int i = t; i < NPTS; i += 1024) {
                int ixj = i ^ j;
                if (ixj > i) {
                    bool up = ((i & k) == 0);
                    float a = sk[i], c = sk[ixj];
                    bool sw = up ? (a > c) : (a < c);
                    if (sw) {
                        sk[i] = c; sk[ixj] = a;
                        int tmp = si[i]; si[i] = si[ixj]; si[ixj] = tmp;
                    }
                }
            }
        }
    }
    __syncthreads();

    for (int i = t; i < NPTS; i += 1024) {
        int id = si[i];
        float px = xb[3*id+0], py = xb[3*id+1], pz = xb[3*id+2];
        g_sp[(size_t)b*NPTS + i] = make_float4(px, py, pz, px*px + py*py + pz*pz);
        g_sid[(size_t)b*NPTS + i] = id;
    }
}

// =====================================================================
// Kernel A: kNN via sorted-axis outward BATCHED scan, exact termination.
//           One thread per query, both directions interleaved.
// =====================================================================
__global__ void __launch_bounds__(SCANT, 1) k_knn()
{
    extern __shared__ unsigned char smem_raw[];
    float4*         spb  = (float4*)smem_raw;                 // [NPTS + 2*PAD]
    float4*         sp   = spb + PAD;
    unsigned short* ssid = (unsigned short*)(spb + NPTS + 2*PAD);

    const int t   = threadIdx.x;
    const int blk = blockIdx.x;
    const int b   = blk / (NPTS/SCANT);                        // batch
    const int pos = (blk % (NPTS/SCANT)) * SCANT + t;          // sorted position

    for (int i = t; i < NPTS; i += SCANT) {
        sp[i]   = g_sp[(size_t)b*NPTS + i];
        ssid[i] = (unsigned short)g_sid[(size_t)b*NPTS + i];
    }
    if (t < PAD) {
        // w = +inf: sentinel score = inf, NEVER <= s[9]  -> never recorded/inserted
        // x = 2e19: dx^2 = inf > bnd (capped 1e37)       -> always terminates scan
        float4 sent = make_float4(2e19f, 0.f, 0.f, __int_as_float(0x7f800000));
        spb[t]        = sent;   // sp[-PAD + t]
        sp[NPTS + t]  = sent;
    }
    __syncthreads();

    const float4 q = sp[pos];
    const float qq  = q.w;
    const float nqx = -2.f*q.x, nqy = -2.f*q.y, nqz = -2.f*q.z;

    float s[10];
    #pragma unroll
    for (int j = 0; j < 10; j++) s[j] = 3.4e38f;
    float bnd = BNDMAX;          // ALWAYS finite: sentinel dx^2 = inf terminates

    unsigned* rec = g_rec + (size_t)(b*NPTS + pos)*CAP;
    int cnt = 0;

    int r = pos, l = pos - 1;
    bool goR = true, goL = true;

    #pragma unroll 1
    while (goR || goL) {
        if (goR) {
            float4 p0 = sp[r];
            float dx0 = p0.x - q.x;
            if (dx0*dx0 > bnd || r >= NPTS) { goR = false; }
            else {
                float4 p1 = sp[r+1], p2 = sp[r+2], p3 = sp[r+3];
                float4 p4 = sp[r+4], p5 = sp[r+5], p6 = sp[r+6], p7 = sp[r+7];
                float s0 = fmaf(p0.z,nqz,fmaf(p0.y,nqy,fmaf(p0.x,nqx,p0.w)));
                float s1 = fmaf(p1.z,nqz,fmaf(p1.y,nqy,fmaf(p1.x,nqx,p1.w)));
                float s2 = fmaf(p2.z,nqz,fmaf(p2.y,nqy,fmaf(p2.x,nqx,p2.w)));
                float s3 = fmaf(p3.z,nqz,fmaf(p3.y,nqy,fmaf(p3.x,nqx,p3.w)));
                float s4 = fmaf(p4.z,nqz,fmaf(p4.y,nqy,fmaf(p4.x,nqx,p4.w)));
                float s5 = fmaf(p5.z,nqz,fmaf(p5.y,nqy,fmaf(p5.x,nqx,p5.w)));
                float s6 = fmaf(p6.z,nqz,fmaf(p6.y,nqy,fmaf(p6.x,nqx,p6.w)));
                float s7 = fmaf(p7.z,nqz,fmaf(p7.y,nqy,fmaf(p7.x,nqx,p7.w)));
                float mn = fminf(fminf(fminf(s0,s1),fminf(s2,s3)),
                                 fminf(fminf(s4,s5),fminf(s6,s7)));
                if (mn <= s[9]) {
                    if (s0 <= s[9]) { if (cnt<CAP) rec[cnt]=r+0; cnt++; if (s0<s[9]) CHAIN_INSERT(s,s0); }
                    if (s1 <= s[9]) { if (cnt<CAP) rec[cnt]=r+1; cnt++; if (s1<s[9]) CHAIN_INSERT(s,s1); }
                    if (s2 <= s[9]) { if (cnt<CAP) rec[cnt]=r+2; cnt++; if (s2<s[9]) CHAIN_INSERT(s,s2); }
                    if (s3 <= s[9]) { if (cnt<CAP) rec[cnt]=r+3; cnt++; if (s3<s[9]) CHAIN_INSERT(s,s3); }
                    if (s4 <= s[9]) { if (cnt<CAP) rec[cnt]=r+4; cnt++; if (s4<s[9]) CHAIN_INSERT(s,s4); }
                    if (s5 <= s[9]) { if (cnt<CAP) rec[cnt]=r+5; cnt++; if (s5<s[9]) CHAIN_INSERT(s,s5); }
                    if (s6 <= s[9]) { if (cnt<CAP) rec[cnt]=r+6; cnt++; if (s6<s[9]) CHAIN_INSERT(s,s6); }
                    if (s7 <= s[9]) { if (cnt<CAP) rec[cnt]=r+7; cnt++; if (s7<s[9]) CHAIN_INSERT(s,s7); }
                    bnd = fminf(fmaf(s[9] + qq, 1.01f, 4e-6f), BNDMAX);
                }
                r += 8;
            }
        }
        if (goL) {
            float4 p0 = sp[l];
            float dx0 = q.x - p0.x;
            if (dx0*dx0 > bnd || l < 0) { goL = false; }
            else {
                float4 p1 = sp[l-1], p2 = sp[l-2], p3 = sp[l-3];
                float4 p4 = sp[l-4], p5 = sp[l-5], p6 = sp[l-6], p7 = sp[l-7];
                float s0 = fmaf(p0.z,nqz,fmaf(p0.y,nqy,fmaf(p0.x,nqx,p0.w)));
                float s1 = fmaf(p1.z,nqz,fmaf(p1.y,nqy,fmaf(p1.x,nqx,p1.w)));
                float s2 = fmaf(p2.z,nqz,fmaf(p2.y,nqy,fmaf(p2.x,nqx,p2.w)));
                float s3 = fmaf(p3.z,nqz,fmaf(p3.y,nqy,fmaf(p3.x,nqx,p3.w)));
                float s4 = fmaf(p4.z,nqz,fmaf(p4.y,nqy,fmaf(p4.x,nqx,p4.w)));
                float s5 = fmaf(p5.z,nqz,fmaf(p5.y,nqy,fmaf(p5.x,nqx,p5.w)));
                float s6 = fmaf(p6.z,nqz,fmaf(p6.y,nqy,fmaf(p6.x,nqx,p6.w)));
                float s7 = fmaf(p7.z,nqz,fmaf(p7.y,nqy,fmaf(p7.x,nqx,p7.w)));
                float mn = fminf(fminf(fminf(s0,s1),fminf(s2,s3)),
                                 fminf(fminf(s4,s5),fminf(s6,s7)));
                if (mn <= s[9]) {
                    if (s0 <= s[9]) { if (cnt<CAP) rec[cnt]=l-0; cnt++; if (s0<s[9]) CHAIN_INSERT(s,s0); }
                    if (s1 <= s[9]) { if (cnt<CAP) rec[cnt]=l-1; cnt++; if (s1<s[9]) CHAIN_INSERT(s,s1); }
                    if (s2 <= s[9]) { if (cnt<CAP) rec[cnt]=l-2; cnt++; if (s2<s[9]) CHAIN_INSERT(s,s2); }
                    if (s3 <= s[9]) { if (cnt<CAP) rec[cnt]=l-3; cnt++; if (s3<s[9]) CHAIN_INSERT(s,s3); }
                    if (s4 <= s[9]) { if (cnt<CAP) rec[cnt]=l-4; cnt++; if (s4<s[9]) CHAIN_INSERT(s,s4); }
                    if (s5 <= s[9]) { if (cnt<CAP) rec[cnt]=l-5; cnt++; if (s5<s[9]) CHAIN_INSERT(s,s5); }
                    if (s6 <= s[9]) { if (cnt<CAP) rec[cnt]=l-6; cnt++; if (s6<s[9]) CHAIN_INSERT(s,s6); }
                    if (s7 <= s[9]) { if (cnt<CAP) rec[cnt]=l-7; cnt++; if (s7<s[9]) CHAIN_INSERT(s,s7); }
                    bnd = fminf(fmaf(s[9] + qq, 1.01f, 4e-6f), BNDMAX);
                }
                l -= 8;
            }
        }
    }

    // ---- exact selection by (value, original id) over recorded superset ----
    float v[10]; int vid[10];
    #pragma unroll
    for (int j = 0; j < 10; j++) { v[j] = 3.4e38f; vid[j] = 0x7fffffff; }

    if (cnt <= CAP) {
        #pragma unroll 1
        for (int j2 = 0; j2 < cnt; j2++) {
            unsigned pp = rec[j2];
            if (pp >= (unsigned)NPTS) continue;      // safety: never true by construction
            float4 p = sp[pp];
            float sv = fmaf(p.z,nqz,fmaf(p.y,nqy,fmaf(p.x,nqx,p.w)));
            lex_insert(v, vid, sv, (int)ssid[pp]);
        }
    } else {
        // exact fallback (deterministic; ~never taken)
        #pragma unroll 1
        for (int i = 0; i < NPTS; i++) {
            float4 p = sp[i];
            float sv = fmaf(p.z,nqz,fmaf(p.y,nqy,fmaf(p.x,nqx,p.w)));
            lex_insert(v, vid, sv, (int)ssid[i]);
        }
    }

    // rank-0 is dropped by the reference ([:, :, 1:]); keep ranks 1..9
    const int qoid = (int)ssid[pos];
    int* dst = g_nbr + (size_t)(b*NPTS + qoid)*KNN;
    #pragma unroll
    for (int j = 1; j < 10; j++) dst[j-1] = vid[j];
}

// =====================================================================
// Kernel B: angular features + GEMM1 + stats1
// =====================================================================
__global__ void __launch_bounds__(TPB) k_feat(const float* __restrict__ x,
                                              const float* __restrict__ W1,
                                              const float* __restrict__ b1)
{
    __shared__ float sW1[70], sB1[10], sRed[(TPB/32)*20];
    const int t = threadIdx.x;
    if (t < 70) sW1[t] = W1[t];
    if (t < 10) sB1[t] = b1[t];
    __syncthreads();

    const int p = blockIdx.x*TPB + t;
    const int b = p / NPTS;
    const int n = p % NPTS;
    const float* xb = x + (size_t)b*NPTS*3;
    const float qx = xb[3*n+0], qy = xb[3*n+1], qz = xb[3*n+2];

    const int* ids = g_nbr + (size_t)p*KNN;
    float rx[KNN], ry[KNN], rz[KNN], ph[KNN];
    #pragma unroll
    for (int j = 0; j < KNN; j++) {
        int id = ids[j];
        rx[j] = xb[3*id+0] - qx;
        ry[j] = xb[3*id+1] - qy;
        rz[j] = xb[3*id+2] - qz;
        ph[j] = atan2f(ry[j], rx[j]);
    }

    #pragma unroll
    for (int pass = 0; pass < KNN-1; pass++) {
        #pragma unroll
        for (int j = 0; j < KNN-1; j++) {
            if (j < KNN-1-pass) {
                if (ph[j+1] < ph[j]) {
                    float tt;
                    tt = ph[j]; ph[j] = ph[j+1]; ph[j+1] = tt;
                    tt = rx[j]; rx[j] = rx[j+1]; rx[j+1] = tt;
                    tt = ry[j]; ry[j] = ry[j+1]; ry[j+1] = tt;
                    tt = rz[j]; rz[j] = rz[j+1]; rz[j+1] = tt;
                }
            }
        }
    }

    float sum[10], sq[10];
    #pragma unroll
    for (int c = 0; c < 10; c++) { sum[c] = 0.f; sq[c] = 0.f; }

    float sgn = 1.f;
    const size_t rowbase = (size_t)p * KNN * 10;
    #pragma unroll
    for (int i = 0; i < KNN; i++) {
        const int i2 = (i+1) % KNN;
        float v1x = rx[i],  v1y = ry[i],  v1z = rz[i];
        float v2x = rx[i2], v2y = ry[i2], v2z = rz[i2];
        float cx = 0.5f*(v1x+v2x), cy = 0.5f*(v1y+v2y), cz = 0.5f*(v1z+v2z);
        float nx = v1y*v2z - v1z*v2y;
        float ny = v1z*v2x - v1x*v2z;
        float nz = v1x*v2y - v1y*v2x;
        float nrm = sqrtf(nx*nx + ny*ny + nz*nz);
        float inv = 1.f/(nrm + 1e-6f);
        nx *= inv; ny *= inv; nz *= inv;
        if (i == 0) sgn = (nx > 0.f) ? 1.f : -1.f;
        nx *= sgn; ny *= sgn; nz *= sgn;
        float pos7 = (nx*cx + ny*cy + nz*cz) * 0.57735026918962576f;

        float f[7] = {cx, cy, cz, nx, ny, nz, pos7};
        #pragma unroll
        for (int c = 0; c < 10; c++) {
            float h = sB1[c];
            #pragma unroll
            for (int ff = 0; ff < 7; ff++) h = fmaf(f[ff], sW1[ff*10 + c], h);
            g_h1[rowbase + i*10 + c] = h;
            sum[c] += h;
            sq[c]  = fmaf(h, h, sq[c]);
        }
    }

    #pragma unroll
    for (int c = 0; c < 10; c++) {
        #pragma unroll
        for (int o = 16; o > 0; o >>= 1) {
            sum[c] += __shfl_down_sync(0xffffffffu, sum[c], o);
            sq[c]  += __shfl_down_sync(0xffffffffu, sq[c],  o);
        }
    }
    const int warp = t >> 5, lane = t & 31;
    if (lane == 0) {
        #pragma unroll
        for (int c = 0; c < 10; c++) {
            sRed[warp*20 + c]      = sum[c];
            sRed[warp*20 + 10 + c] = sq[c];
        }
    }
    __syncthreads();
    if (t < 20) {
        float acc = 0.f;
        #pragma unroll
        for (int w = 0; w < TPB/32; w++) acc += sRed[w*20 + t];
        g_part1[blockIdx.x*20 + t] = acc;
    }
}

// =====================================================================
// Parallel BN-stats finalize
// =====================================================================
__device__ __forceinline__ void fin_body(const float* __restrict__ part, int nblk,
                                         const float* __restrict__ g,
                                         const float* __restrict__ be,
                                         float* __restrict__ coef)
{
    __shared__ float red[32*20];
    __shared__ float tot[20];
    const int t = threadIdx.x;
    const int c = t % 20, sub = t / 20;
    float acc = 0.f;
    for (int k = sub; k < nblk; k += 32) acc += part[k*20 + c];
    red[sub*20 + c] = acc;
    __syncthreads();
    if (t < 20) {
        float s = 0.f;
        #pragma unroll
        for (int w = 0; w < 32; w++) s += red[w*20 + t];
        tot[t] = s;
    }
    __syncthreads();
    if (t < 10) {
        float mu  = tot[t] / (float)NROWS;
        float var = tot[10 + t] / (float)NROWS - mu*mu;
        float a   = g[t] * rsqrtf(var + EPS_BN);
        coef[t]      = a;
        coef[10 + t] = be[t] - mu*a;
    }
}

__global__ void k_fin1(const float* __restrict__ g1, const float* __restrict__ be1)
{ fin_body(g_part1, NB1, g1, be1, g_coef1); }

__global__ void k_fin2(const float* __restrict__ g2, const float* __restrict__ be2)
{ fin_body(g_part2, NB3, g2, be2, g_coef2); }

// =====================================================================
// Kernel 3: BN1 + relu + GEMM2 + stats2  (float2 I/O)
// =====================================================================
__global__ void __launch_bounds__(TPB) k_mlp2(const float* __restrict__ W2,
                                              const float* __restrict__ b2)
{
    __shared__ float sW2[100], sB2[10], sA[10], sC[10], sRed[(TPB/32)*20];
    const int t = threadIdx.x;
    if (t < 100) sW2[t] = W2[t];
    if (t < 10) { sB2[t] = b2[t]; sA[t] = g_coef1[t]; sC[t] = g_coef1[10+t]; }
    __syncthreads();

    const size_t row = (size_t)blockIdx.x*TPB + t;
    const float2* src2 = (const float2*)(g_h1 + row*10);

    float h[10];
    #pragma unroll
    for (int c = 0; c < 5; c++) {
        float2 v = src2[c];
        h[2*c+0] = fmaxf(fmaf(v.x, sA[2*c+0], sC[2*c+0]), 0.f);
        h[2*c+1] = fmaxf(fmaf(v.y, sA[2*c+1], sC[2*c+1]), 0.f);
    }

    float sum[10], sq[10];
    float2* dst2 = (float2*)(g_h2 + row*10);
    #pragma unroll
    for (int c2 = 0; c2 < 10; c2++) {
        float z = sB2[c2];
        #pragma unroll
        for (int c = 0; c < 10; c++) z = fmaf(h[c], sW2[c*10 + c2], z);
        sum[c2] = z;
        sq[c2]  = z*z;
    }
    #pragma unroll
    for (int c = 0; c < 5; c++) dst2[c] = make_float2(sum[2*c], sum[2*c+1]);

    #pragma unroll
    for (int c = 0; c < 10; c++) {
        #pragma unroll
        for (int o = 16; o > 0; o >>= 1) {
            sum[c] += __shfl_down_sync(0xffffffffu, sum[c], o);
            sq[c]  += __shfl_down_sync(0xffffffffu, sq[c],  o);
        }
    }
    const int warp = t >> 5, lane = t & 31;
    if (lane == 0) {
        #pragma unroll
        for (int c = 0; c < 10; c++) {
            sRed[warp*20 + c]      = sum[c];
            sRed[warp*20 + 10 + c] = sq[c];
        }
    }
    __syncthreads();
    if (t < 20) {
        float acc = 0.f;
        #pragma unroll
        for (int w = 0; w < TPB/32; w++) acc += sRed[w*20 + t];
        g_part2[blockIdx.x*20 + t] = acc;
    }
}

// =====================================================================
// Kernel 5: BN2 + relu + max over k  (float2 I/O)
// =====================================================================
__global__ void __launch_bounds__(TPB) k_out(float* __restrict__ out)
{
    __shared__ float sA[10], sC[10];
    if (threadIdx.x < 10) { sA[threadIdx.x] = g_coef2[threadIdx.x]; sC[threadIdx.x] = g_coef2[10+threadIdx.x]; }
    __syncthreads();

    const size_t p = (size_t)blockIdx.x*TPB + threadIdx.x;
    const float2* src2 = (const float2*)(g_h2 + p*KNN*10);

    float mx[10];
    #pragma unroll
    for (int c = 0; c < 10; c++) mx[c] = 0.f;

    #pragma unroll
    for (int i = 0; i < KNN; i++) {
        #pragma unroll
        for (int c = 0; c < 5; c++) {
            float2 v = src2[i*5 + c];
            mx[2*c+0] = fmaxf(mx[2*c+0], fmaxf(fmaf(v.x, sA[2*c+0], sC[2*c+0]), 0.f));
            mx[2*c+1] = fmaxf(mx[2*c+1], fmaxf(fmaf(v.y, sA[2*c+1], sC[2*c+1]), 0.f));
        }
    }
    float2* o2 = (float2*)(out + p*10);
    #pragma unroll
    for (int c = 0; c < 5; c++) o2[c] = make_float2(mx[2*c], mx[2*c+1]);
}

// =====================================================================
extern "C" void kernel_launch(void* const* d_in, const int* in_sizes, int n_in,
                              void* d_out, int out_size)
{
    const float* x   = (const float*)d_in[0];
    const float* W1  = (const float*)d_in[1];
    const float* b1  = (const float*)d_in[2];
    const float* g1  = (const float*)d_in[3];
    const float* be1 = (const float*)d_in[4];
    const float* W2  = (const float*)d_in[5];
    const float* b2  = (const float*)d_in[6];
    const float* g2  = (const float*)d_in[7];
    const float* be2 = (const float*)d_in[8];
    float* out = (float*)d_out;

    const size_t smemSort = (size_t)NPTS*(sizeof(float)+sizeof(int));            // 64KB
    const size_t smemKnn  = (size_t)(NPTS + 2*PAD)*sizeof(float4)
                          + (size_t)NPTS*sizeof(unsigned short);                 // ~144.3KB
    cudaFuncSetAttribute(k_sort, cudaFuncAttributeMaxDynamicSharedMemorySize, (int)smemSort);
    cudaFuncSetAttribute(k_knn,  cudaFuncAttributeMaxDynamicSharedMemorySize, (int)smemKnn);

    k_sort<<<B_, 1024, smemSort>>>(x);
    k_knn<<<NPOINTS/SCANT, SCANT, smemKnn>>>();
    k_feat<<<NB1, TPB>>>(x, W1, b1);
    k_fin1<<<1, 640>>>(g1, be1);
    k_mlp2<<<NB3, TPB>>>(W2, b2);
    k_fin2<<<1, 640>>>(g2, be2);
    k_out<<<NPOINTS/TPB, TPB>>>(out);
}

// round 11
// speedup vs baseline: 1.8649x; 1.2035x over previous
#include <cuda_runtime.h>
#include <math.h>

#define B_    4
#define NPTS  8192
#define KNN   9
#define TPB   256
#define SCANT 256                  // scan threads/block = queries/block
#define PAD   8
#define CAP   192                  // record capacity per query
#define BNDMAX 1e37f               // finite bound cap (sentinel dx^2 = inf always exceeds)
#define KB_   2048                 // counting-sort buckets
#define NPOINTS (B_*NPTS)          // 32768
#define NROWS   (NPOINTS*KNN)      // 294912
#define NB1     (NPOINTS/TPB)      // 128
#define NB3     (NROWS/TPB)        // 1152
#define EPS_BN  1e-5f

// ---- scratch (static device memory; no allocations) ----
__device__ float4   g_sp[NPOINTS];                 // sorted points (x,y,z,|p|^2)
__device__ int      g_sid[NPOINTS];                // sorted pos -> original id
__device__ unsigned g_rec[(size_t)NPOINTS*CAP];    // insert-event records
__device__ int      g_nbr[(size_t)NPOINTS*KNN];
__device__ __align__(16) float g_h1[(size_t)NROWS*10];
__device__ __align__(16) float g_h2[(size_t)NROWS*10];
__device__ float g_part1[NB1*20];
__device__ float g_part2[NB3*20];
__device__ float g_coef1[20];
__device__ float g_coef2[20];

// branchless insert of one value into sorted-ascending s[0..9] (values only)
#define CHAIN_INSERT(sarr, val) do {                 \
    float _c = (val);                                \
    _Pragma("unroll")                                \
    for (int _j = 0; _j < 10; _j++) {                \
        float _lo = fminf(sarr[_j], _c);             \
        _c = fmaxf(sarr[_j], _c);                    \
        sarr[_j] = _lo;                              \
    }                                                \
} while (0)

// exact lexicographic (value, id) insert into ascending (v, vid)[0..9]
__device__ __forceinline__ void lex_insert(float* v, int* vid, float sv, int oid) {
    if (sv < v[9] || (sv == v[9] && oid < vid[9])) {
        float cs = sv; int ci = oid;
        #pragma unroll
        for (int j = 0; j < 10; j++) {
            bool take = (cs < v[j]) || (cs == v[j] && ci < vid[j]);
            float tv = take ? cs : v[j];
            float uv = take ? v[j] : cs;
            int   ti = take ? ci : vid[j];
            int   ui = take ? vid[j] : ci;
            v[j] = tv; vid[j] = ti; cs = uv; ci = ui;
        }
    }
}

// =====================================================================
// Kernel 0: per-batch COUNTING sort by x (exact final order by (x,id))
// =====================================================================
__global__ void __launch_bounds__(1024) k_csort(const float* __restrict__ x)
{
    extern __shared__ unsigned char smem_raw[];
    unsigned*       hist  = (unsigned*)smem_raw;               // [KB_]
    unsigned*       offs  = hist + KB_;                        // [KB_]
    unsigned*       cur   = offs + KB_;                        // [KB_]
    unsigned*       chunk = cur  + KB_;                        // [32]
    float*          keyx  = (float*)(chunk + 32);              // [NPTS]
    unsigned short* kid   = (unsigned short*)(keyx + NPTS);    // [NPTS]

    const int b = blockIdx.x;
    const int t = threadIdx.x;
    const float* xb = x + (size_t)b*NPTS*3;

    for (int i = t; i < KB_; i += 1024) { hist[i] = 0u; cur[i] = 0u; }
    __syncthreads();

    const float lo = -6.f;
    const float invw = (float)KB_ / 12.f;

    for (int i = t; i < NPTS; i += 1024) {
        float px = xb[3*i];
        int bi = (int)floorf((px - lo) * invw);
        bi = min(max(bi, 0), KB_-1);
        atomicAdd(&hist[bi], 1u);
    }
    __syncthreads();

    // prefix sum: 32 threads x 64 bins, then serial scan of 32 partials
    if (t < 32) {
        unsigned s = 0;
        for (int j = 0; j < 64; j++) s += hist[t*64 + j];
        chunk[t] = s;
    }
    __syncthreads();
    if (t == 0) {
        unsigned s = 0;
        for (int j = 0; j < 32; j++) { unsigned c = chunk[j]; chunk[j] = s; s += c; }
    }
    __syncthreads();
    if (t < 32) {
        unsigned s = chunk[t];
        for (int j = 0; j < 64; j++) { unsigned c = hist[t*64 + j]; offs[t*64 + j] = s; s += c; }
    }
    __syncthreads();

    // scatter (slot order within bucket nondeterministic; fixed by sort below)
    for (int i = t; i < NPTS; i += 1024) {
        float px = xb[3*i];
        int bi = (int)floorf((px - lo) * invw);
        bi = min(max(bi, 0), KB_-1);
        unsigned slot = offs[bi] + atomicAdd(&cur[bi], 1u);
        keyx[slot] = px;
        kid[slot]  = (unsigned short)i;
    }
    __syncthreads();

    // per-bucket insertion sort by (x, id) -> exact deterministic order
    for (int bb = t; bb < KB_; bb += 1024) {
        int s0 = (int)offs[bb];
        int s1 = s0 + (int)hist[bb];
        for (int i2 = s0 + 1; i2 < s1; i2++) {
            float kx = keyx[i2]; unsigned short ki = kid[i2];
            int j = i2 - 1;
            while (j >= s0 && (keyx[j] > kx || (keyx[j] == kx && kid[j] > ki))) {
                keyx[j+1] = keyx[j]; kid[j+1] = kid[j]; j--;
            }
            keyx[j+1] = kx; kid[j+1] = ki;
        }
    }
    __syncthreads();

    for (int i = t; i < NPTS; i += 1024) {
        int id = (int)kid[i];
        float px = xb[3*id+0], py = xb[3*id+1], pz = xb[3*id+2];
        g_sp[(size_t)b*NPTS + i] = make_float4(px, py, pz, px*px + py*py + pz*pz);
        g_sid[(size_t)b*NPTS + i] = id;
    }
}

// =====================================================================
// Kernel A: kNN via sorted-axis outward BATCHED scan, exact termination.
//           One thread per query, both directions interleaved.
// =====================================================================
__global__ void __launch_bounds__(SCANT, 1) k_knn()
{
    extern __shared__ unsigned char smem_raw[];
    float4*         spb  = (float4*)smem_raw;                 // [NPTS + 2*PAD]
    float4*         sp   = spb + PAD;
    unsigned short* ssid = (unsigned short*)(spb + NPTS + 2*PAD);

    const int t   = threadIdx.x;
    const int blk = blockIdx.x;
    const int b   = blk / (NPTS/SCANT);                        // batch
    const int pos = (blk % (NPTS/SCANT)) * SCANT + t;          // sorted position

    for (int i = t; i < NPTS; i += SCANT) {
        sp[i]   = g_sp[(size_t)b*NPTS + i];
        ssid[i] = (unsigned short)g_sid[(size_t)b*NPTS + i];
    }
    if (t < PAD) {
        // w = +inf: sentinel score = inf, NEVER <= s[9]  -> never recorded/inserted
        // x = 2e19: dx^2 = inf > bnd (capped 1e37)       -> always terminates scan
        float4 sent = make_float4(2e19f, 0.f, 0.f, __int_as_float(0x7f800000));
        spb[t]        = sent;   // sp[-PAD + t]
        sp[NPTS + t]  = sent;
    }
    __syncthreads();

    const float4 q = sp[pos];
    const float qq  = q.w;
    const float nqx = -2.f*q.x, nqy = -2.f*q.y, nqz = -2.f*q.z;

    float s[10];
    #pragma unroll
    for (int j = 0; j < 10; j++) s[j] = 3.4e38f;
    float bnd = BNDMAX;          // ALWAYS finite: sentinel dx^2 = inf terminates

    unsigned* rec = g_rec + (size_t)(b*NPTS + pos)*CAP;
    int cnt = 0;

    int r = pos, l = pos - 1;
    bool goR = true, goL = true;

    #pragma unroll 1
    while (goR || goL) {
        if (goR) {
            float4 p0 = sp[r];
            float dx0 = p0.x - q.x;
            if (dx0*dx0 > bnd || r >= NPTS) { goR = false; }
            else {
                float4 p1 = sp[r+1], p2 = sp[r+2], p3 = sp[r+3];
                float4 p4 = sp[r+4], p5 = sp[r+5], p6 = sp[r+6], p7 = sp[r+7];
                float s0 = fmaf(p0.z,nqz,fmaf(p0.y,nqy,fmaf(p0.x,nqx,p0.w)));
                float s1 = fmaf(p1.z,nqz,fmaf(p1.y,nqy,fmaf(p1.x,nqx,p1.w)));
                float s2 = fmaf(p2.z,nqz,fmaf(p2.y,nqy,fmaf(p2.x,nqx,p2.w)));
                float s3 = fmaf(p3.z,nqz,fmaf(p3.y,nqy,fmaf(p3.x,nqx,p3.w)));
                float s4 = fmaf(p4.z,nqz,fmaf(p4.y,nqy,fmaf(p4.x,nqx,p4.w)));
                float s5 = fmaf(p5.z,nqz,fmaf(p5.y,nqy,fmaf(p5.x,nqx,p5.w)));
                float s6 = fmaf(p6.z,nqz,fmaf(p6.y,nqy,fmaf(p6.x,nqx,p6.w)));
                float s7 = fmaf(p7.z,nqz,fmaf(p7.y,nqy,fmaf(p7.x,nqx,p7.w)));
                float mn = fminf(fminf(fminf(s0,s1),fminf(s2,s3)),
                                 fminf(fminf(s4,s5),fminf(s6,s7)));
                if (mn <= s[9]) {
                    if (s0 <= s[9]) { if (cnt<CAP) rec[cnt]=r+0; cnt++; if (s0<s[9]) CHAIN_INSERT(s,s0); }
                    if (s1 <= s[9]) { if (cnt<CAP) rec[cnt]=r+1; cnt++; if (s1<s[9]) CHAIN_INSERT(s,s1); }
                    if (s2 <= s[9]) { if (cnt<CAP) rec[cnt]=r+2; cnt++; if (s2<s[9]) CHAIN_INSERT(s,s2); }
                    if (s3 <= s[9]) { if (cnt<CAP) rec[cnt]=r+3; cnt++; if (s3<s[9]) CHAIN_INSERT(s,s3); }
                    if (s4 <= s[9]) { if (cnt<CAP) rec[cnt]=r+4; cnt++; if (s4<s[9]) CHAIN_INSERT(s,s4); }
                    if (s5 <= s[9]) { if (cnt<CAP) rec[cnt]=r+5; cnt++; if (s5<s[9]) CHAIN_INSERT(s,s5); }
                    if (s6 <= s[9]) { if (cnt<CAP) rec[cnt]=r+6; cnt++; if (s6<s[9]) CHAIN_INSERT(s,s6); }
                    if (s7 <= s[9]) { if (cnt<CAP) rec[cnt]=r+7; cnt++; if (s7<s[9]) CHAIN_INSERT(s,s7); }
                    bnd = fminf(fmaf(s[9] + qq, 1.01f, 4e-6f), BNDMAX);
                }
                r += 8;
            }
        }
        if (goL) {
            float4 p0 = sp[l];
            float dx0 = q.x - p0.x;
            if (dx0*dx0 > bnd || l < 0) { goL = false; }
            else {
                float4 p1 = sp[l-1], p2 = sp[l-2], p3 = sp[l-3];
                float4 p4 = sp[l-4], p5 = sp[l-5], p6 = sp[l-6], p7 = sp[l-7];
                float s0 = fmaf(p0.z,nqz,fmaf(p0.y,nqy,fmaf(p0.x,nqx,p0.w)));
                float s1 = fmaf(p1.z,nqz,fmaf(p1.y,nqy,fmaf(p1.x,nqx,p1.w)));
                float s2 = fmaf(p2.z,nqz,fmaf(p2.y,nqy,fmaf(p2.x,nqx,p2.w)));
                float s3 = fmaf(p3.z,nqz,fmaf(p3.y,nqy,fmaf(p3.x,nqx,p3.w)));
                float s4 = fmaf(p4.z,nqz,fmaf(p4.y,nqy,fmaf(p4.x,nqx,p4.w)));
                float s5 = fmaf(p5.z,nqz,fmaf(p5.y,nqy,fmaf(p5.x,nqx,p5.w)));
                float s6 = fmaf(p6.z,nqz,fmaf(p6.y,nqy,fmaf(p6.x,nqx,p6.w)));
                float s7 = fmaf(p7.z,nqz,fmaf(p7.y,nqy,fmaf(p7.x,nqx,p7.w)));
                float mn = fminf(fminf(fminf(s0,s1),fminf(s2,s3)),
                                 fminf(fminf(s4,s5),fminf(s6,s7)));
                if (mn <= s[9]) {
                    if (s0 <= s[9]) { if (cnt<CAP) rec[cnt]=l-0; cnt++; if (s0<s[9]) CHAIN_INSERT(s,s0); }
                    if (s1 <= s[9]) { if (cnt<CAP) rec[cnt]=l-1; cnt++; if (s1<s[9]) CHAIN_INSERT(s,s1); }
                    if (s2 <= s[9]) { if (cnt<CAP) rec[cnt]=l-2; cnt++; if (s2<s[9]) CHAIN_INSERT(s,s2); }
                    if (s3 <= s[9]) { if (cnt<CAP) rec[cnt]=l-3; cnt++; if (s3<s[9]) CHAIN_INSERT(s,s3); }
                    if (s4 <= s[9]) { if (cnt<CAP) rec[cnt]=l-4; cnt++; if (s4<s[9]) CHAIN_INSERT(s,s4); }
                    if (s5 <= s[9]) { if (cnt<CAP) rec[cnt]=l-5; cnt++; if (s5<s[9]) CHAIN_INSERT(s,s5); }
                    if (s6 <= s[9]) { if (cnt<CAP) rec[cnt]=l-6; cnt++; if (s6<s[9]) CHAIN_INSERT(s,s6); }
                    if (s7 <= s[9]) { if (cnt<CAP) rec[cnt]=l-7; cnt++; if (s7<s[9]) CHAIN_INSERT(s,s7); }
                    bnd = fminf(fmaf(s[9] + qq, 1.01f, 4e-6f), BNDMAX);
                }
                l -= 8;
            }
        }
    }

    // ---- exact selection by (value, original id) over recorded superset ----
    float v[10]; int vid[10];
    #pragma unroll
    for (int j = 0; j < 10; j++) { v[j] = 3.4e38f; vid[j] = 0x7fffffff; }

    if (cnt <= CAP) {
        #pragma unroll 1
        for (int j2 = 0; j2 < cnt; j2++) {
            unsigned pp = rec[j2];
            if (pp >= (unsigned)NPTS) continue;      // safety: never true by construction
            float4 p = sp[pp];
            float sv = fmaf(p.z,nqz,fmaf(p.y,nqy,fmaf(p.x,nqx,p.w)));
            lex_insert(v, vid, sv, (int)ssid[pp]);
        }
    } else {
        // exact fallback (deterministic; ~never taken)
        #pragma unroll 1
        for (int i = 0; i < NPTS; i++) {
            float4 p = sp[i];
            float sv = fmaf(p.z,nqz,fmaf(p.y,nqy,fmaf(p.x,nqx,p.w)));
            lex_insert(v, vid, sv, (int)ssid[i]);
        }
    }

    // rank-0 is dropped by the reference ([:, :, 1:]); keep ranks 1..9
    const int qoid = (int)ssid[pos];
    int* dst = g_nbr + (size_t)(b*NPTS + qoid)*KNN;
    #pragma unroll
    for (int j = 1; j < 10; j++) dst[j-1] = vid[j];
}

// =====================================================================
// Kernel B: angular features + GEMM1 + stats1
// =====================================================================
__global__ void __launch_bounds__(TPB) k_feat(const float* __restrict__ x,
                                              const float* __restrict__ W1,
                                              const float* __restrict__ b1)
{
    __shared__ float sW1[70], sB1[10], sRed[(TPB/32)*20];
    const int t = threadIdx.x;
    if (t < 70) sW1[t] = W1[t];
    if (t < 10) sB1[t] = b1[t];
    __syncthreads();

    const int p = blockIdx.x*TPB + t;
    const int b = p / NPTS;
    const int n = p % NPTS;
    const float* xb = x + (size_t)b*NPTS*3;
    const float qx = xb[3*n+0], qy = xb[3*n+1], qz = xb[3*n+2];

    const int* ids = g_nbr + (size_t)p*KNN;
    float rx[KNN], ry[KNN], rz[KNN], ph[KNN];
    #pragma unroll
    for (int j = 0; j < KNN; j++) {
        int id = ids[j];
        rx[j] = xb[3*id+0] - qx;
        ry[j] = xb[3*id+1] - qy;
        rz[j] = xb[3*id+2] - qz;
        ph[j] = atan2f(ry[j], rx[j]);
    }

    #pragma unroll
    for (int pass = 0; pass < KNN-1; pass++) {
        #pragma unroll
        for (int j = 0; j < KNN-1; j++) {
            if (j < KNN-1-pass) {
                if (ph[j+1] < ph[j]) {
                    float tt;
                    tt = ph[j]; ph[j] = ph[j+1]; ph[j+1] = tt;
                    tt = rx[j]; rx[j] = rx[j+1]; rx[j+1] = tt;
                    tt = ry[j]; ry[j] = ry[j+1]; ry[j+1] = tt;
                    tt = rz[j]; rz[j] = rz[j+1]; rz[j+1] = tt;
                }
            }
        }
    }

    float sum[10], sq[10];
    #pragma unroll
    for (int c = 0; c < 10; c++) { sum[c] = 0.f; sq[c] = 0.f; }

    float sgn = 1.f;
    const size_t rowbase = (size_t)p * KNN * 10;
    #pragma unroll
    for (int i = 0; i < KNN; i++) {
        const int i2 = (i+1) % KNN;
        float v1x = rx[i],  v1y = ry[i],  v1z = rz[i];
        float v2x = rx[i2], v2y = ry[i2], v2z = rz[i2];
        float cx = 0.5f*(v1x+v2x), cy = 0.5f*(v1y+v2y), cz = 0.5f*(v1z+v2z);
        float nx = v1y*v2z - v1z*v2y;
        float ny = v1z*v2x - v1x*v2z;
        float nz = v1x*v2y - v1y*v2x;
        float nrm = sqrtf(nx*nx + ny*ny + nz*nz);
        float inv = 1.f/(nrm + 1e-6f);
        nx *= inv; ny *= inv; nz *= inv;
        if (i == 0) sgn = (nx > 0.f) ? 1.f : -1.f;
        nx *= sgn; ny *= sgn; nz *= sgn;
        float pos7 = (nx*cx + ny*cy + nz*cz) * 0.57735026918962576f;

        float f[7] = {cx, cy, cz, nx, ny, nz, pos7};
        #pragma unroll
        for (int c = 0; c < 10; c++) {
            float h = sB1[c];
            #pragma unroll
            for (int ff = 0; ff < 7; ff++) h = fmaf(f[ff], sW1[ff*10 + c], h);
            g_h1[rowbase + i*10 + c] = h;
            sum[c] += h;
            sq[c]  = fmaf(h, h, sq[c]);
        }
    }

    #pragma unroll
    for (int c = 0; c < 10; c++) {
        #pragma unroll
        for (int o = 16; o > 0; o >>= 1) {
            sum[c] += __shfl_down_sync(0xffffffffu, sum[c], o);
            sq[c]  += __shfl_down_sync(0xffffffffu, sq[c],  o);
        }
    }
    const int warp = t >> 5, lane = t & 31;
    if (lane == 0) {
        #pragma unroll
        for (int c = 0; c < 10; c++) {
            sRed[warp*20 + c]      = sum[c];
            sRed[warp*20 + 10 + c] = sq[c];
        }
    }
    __syncthreads();
    if (t < 20) {
        float acc = 0.f;
        #pragma unroll
        for (int w = 0; w < TPB/32; w++) acc += sRed[w*20 + t];
        g_part1[blockIdx.x*20 + t] = acc;
    }
}

// =====================================================================
// Parallel BN-stats finalize
// =====================================================================
__device__ __forceinline__ void fin_body(const float* __restrict__ part, int nblk,
                                         const float* __restrict__ g,
                                         const float* __restrict__ be,
                                         float* __restrict__ coef)
{
    __shared__ float red[32*20];
    __shared__ float tot[20];
    const int t = threadIdx.x;
    const int c = t % 20, sub = t / 20;
    float acc = 0.f;
    for (int k = sub; k < nblk; k += 32) acc += part[k*20 + c];
    red[sub*20 + c] = acc;
    __syncthreads();
    if (t < 20) {
        float s = 0.f;
        #pragma unroll
        for (int w = 0; w < 32; w++) s += red[w*20 + t];
        tot[t] = s;
    }
    __syncthreads();
    if (t < 10) {
        float mu  = tot[t] / (float)NROWS;
        float var = tot[10 + t] / (float)NROWS - mu*mu;
        float a   = g[t] * rsqrtf(var + EPS_BN);
        coef[t]      = a;
        coef[10 + t] = be[t] - mu*a;
    }
}

__global__ void k_fin1(const float* __restrict__ g1, const float* __restrict__ be1)
{ fin_body(g_part1, NB1, g1, be1, g_coef1); }

__global__ void k_fin2(const float* __restrict__ g2, const float* __restrict__ be2)
{ fin_body(g_part2, NB3, g2, be2, g_coef2); }

// =====================================================================
// Kernel 3: BN1 + relu + GEMM2 + stats2  (float2 I/O)
// =====================================================================
__global__ void __launch_bounds__(TPB) k_mlp2(const float* __restrict__ W2,
                                              const float* __restrict__ b2)
{
    __shared__ float sW2[100], sB2[10], sA[10], sC[10], sRed[(TPB/32)*20];
    const int t = threadIdx.x;
    if (t < 100) sW2[t] = W2[t];
    if (t < 10) { sB2[t] = b2[t]; sA[t] = g_coef1[t]; sC[t] = g_coef1[10+t]; }
    __syncthreads();

    const size_t row = (size_t)blockIdx.x*TPB + t;
    const float2* src2 = (const float2*)(g_h1 + row*10);

    float h[10];
    #pragma unroll
    for (int c = 0; c < 5; c++) {
        float2 v = src2[c];
        h[2*c+0] = fmaxf(fmaf(v.x, sA[2*c+0], sC[2*c+0]), 0.f);
        h[2*c+1] = fmaxf(fmaf(v.y, sA[2*c+1], sC[2*c+1]), 0.f);
    }

    float sum[10], sq[10];
    float2* dst2 = (float2*)(g_h2 + row*10);
    #pragma unroll
    for (int c2 = 0; c2 < 10; c2++) {
        float z = sB2[c2];
        #pragma unroll
        for (int c = 0; c < 10; c++) z = fmaf(h[c], sW2[c*10 + c2], z);
        sum[c2] = z;
        sq[c2]  = z*z;
    }
    #pragma unroll
    for (int c = 0; c < 5; c++) dst2[c] = make_float2(sum[2*c], sum[2*c+1]);

    #pragma unroll
    for (int c = 0; c < 10; c++) {
        #pragma unroll
        for (int o = 16; o > 0; o >>= 1) {
            sum[c] += __shfl_down_sync(0xffffffffu, sum[c], o);
            sq[c]  += __shfl_down_sync(0xffffffffu, sq[c],  o);
        }
    }
    const int warp = t >> 5, lane = t & 31;
    if (lane == 0) {
        #pragma unroll
        for (int c = 0; c < 10; c++) {
            sRed[warp*20 + c]      = sum[c];
            sRed[warp*20 + 10 + c] = sq[c];
        }
    }
    __syncthreads();
    if (t < 20) {
        float acc = 0.f;
        #pragma unroll
        for (int w = 0; w < TPB/32; w++) acc += sRed[w*20 + t];
        g_part2[blockIdx.x*20 + t] = acc;
    }
}

// =====================================================================
// Kernel 5: BN2 + relu + max over k  (float2 I/O)
// =====================================================================
__global__ void __launch_bounds__(TPB) k_out(float* __restrict__ out)
{
    __shared__ float sA[10], sC[10];
    if (threadIdx.x < 10) { sA[threadIdx.x] = g_coef2[threadIdx.x]; sC[threadIdx.x] = g_coef2[10+threadIdx.x]; }
    __syncthreads();

    const size_t p = (size_t)blockIdx.x*TPB + threadIdx.x;
    const float2* src2 = (const float2*)(g_h2 + p*KNN*10);

    float mx[10];
    #pragma unroll
    for (int c = 0; c < 10; c++) mx[c] = 0.f;

    #pragma unroll
    for (int i = 0; i < KNN; i++) {
        #pragma unroll
        for (int c = 0; c < 5; c++) {
            float2 v = src2[i*5 + c];
            mx[2*c+0] = fmaxf(mx[2*c+0], fmaxf(fmaf(v.x, sA[2*c+0], sC[2*c+0]), 0.f));
            mx[2*c+1] = fmaxf(mx[2*c+1], fmaxf(fmaf(v.y, sA[2*c+1], sC[2*c+1]), 0.f));
        }
    }
    float2* o2 = (float2*)(out + p*10);
    #pragma unroll
    for (int c = 0; c < 5; c++) o2[c] = make_float2(mx[2*c], mx[2*c+1]);
}

// =====================================================================
extern "C" void kernel_launch(void* const* d_in, const int* in_sizes, int n_in,
                              void* d_out, int out_size)
{
    const float* x   = (const float*)d_in[0];
    const float* W1  = (const float*)d_in[1];
    const float* b1  = (const float*)d_in[2];
    const float* g1  = (const float*)d_in[3];
    const float* be1 = (const float*)d_in[4];
    const float* W2  = (const float*)d_in[5];
    const float* b2  = (const float*)d_in[6];
    const float* g2  = (const float*)d_in[7];
    const float* be2 = (const float*)d_in[8];
    float* out = (float*)d_out;

    const size_t smemSort = (size_t)(3*KB_ + 32 + NPTS)*sizeof(unsigned)
                          + (size_t)NPTS*sizeof(unsigned short);                 // ~72.2KB
    const size_t smemKnn  = (size_t)(NPTS + 2*PAD)*sizeof(float4)
                          + (size_t)NPTS*sizeof(unsigned short);                 // ~144.3KB
    cudaFuncSetAttribute(k_csort, cudaFuncAttributeMaxDynamicSharedMemorySize, (int)smemSort);
    cudaFuncSetAttribute(k_knn,   cudaFuncAttributeMaxDynamicSharedMemorySize, (int)smemKnn);

    k_csort<<<B_, 1024, smemSort>>>(x);
    k_knn<<<NPOINTS/SCANT, SCANT, smemKnn>>>();
    k_feat<<<NB1, TPB>>>(x, W1, b1);
    k_fin1<<<1, 640>>>(g1, be1);
    k_mlp2<<<NB3, TPB>>>(W2, b2);
    k_fin2<<<1, 640>>>(g2, be2);
    k_out<<<NPOINTS/TPB, TPB>>>(out);
}